// round 16
// baseline (speedup 1.0000x reference)
#include <cuda_runtime.h>
#include <cuda_bf16.h>
#include <cuda_fp16.h>
#include <math.h>

#define NB 1024   // batches
#define NN 64     // nodes
#define DD 128    // feature dim
#define EE 1024   // edges
#define HH 4      // heads
#define KK 5
#define LL 2
#define NT 512    // threads per CTA
#define NW 16     // warps per CTA

// Edge data sorted by dst (CSR order), built once per launch
__device__ int   g_off[NN + 1];
__device__ int   g_srcp[EE];
__device__ float g_eap[EE];

// W matrices as fp16 hi/lo packed in m16n8k16 B-fragment order:
// mat m: slot s = (ks*16 + ct)*32 + lane; u32[4] = {bhi0, bhi1, blo0, blo1}
// mats: 0=Wl0 1=Wr0 2=Wl1 3=Wr1 4=W1[0:128] 5=W1[128:256]
__device__ unsigned g_Bpack[6 * 16384];

__device__ __forceinline__ unsigned packh2(__half a, __half b) {
    __half2 h; h.x = a; h.y = b;
    return *(const unsigned*)&h;
}

// Merged setup: block 0 = parallel stable CSR build, blocks 1..6 = W packing.
__global__ __launch_bounds__(EE) void setup_kernel(const int* __restrict__ ei,
                                                   const float* __restrict__ ea,
                                                   const float* __restrict__ Wl,
                                                   const float* __restrict__ Wr,
                                                   const float* __restrict__ W1) {
    if (blockIdx.x == 0) {
        // Stable bucket sort by dst, O(1)-depth per edge:
        // rank = chunk-prefix(dst) + rank-within-32-edge-chunk (via match_any).
        __shared__ int cnt[32][NN];    // per-chunk per-dst counts -> exclusive prefix
        __shared__ int deg[NN];
        __shared__ int off[NN + 1];
        const int e = threadIdx.x;     // 0..1023
        const int chunk = e >> 5;
        const int lane = e & 31;
        for (int i = e; i < 32 * NN; i += EE) (&cnt[0][0])[i] = 0;
        __syncthreads();
        const int d = ei[EE + e];
        const unsigned mm = __match_any_sync(0xffffffffu, d);
        const int rank_in_chunk = __popc(mm & ((1u << lane) - 1u));
        if ((int)(__ffs(mm) - 1) == lane) cnt[chunk][d] = __popc(mm);
        __syncthreads();
        if (e < NN) {
            int run = 0;
#pragma unroll 4
            for (int c = 0; c < 32; ++c) {
                const int t = cnt[c][e];
                cnt[c][e] = run;
                run += t;
            }
            deg[e] = run;
        }
        __syncthreads();
        if (e == 0) {
            int s = 0;
            for (int i = 0; i < NN; ++i) { off[i] = s; s += deg[i]; }
            off[NN] = s;
        }
        __syncthreads();
        const int p = off[d] + cnt[chunk][d] + rank_in_chunk;
        g_srcp[p] = ei[e];
        g_eap[p]  = ea[e];
        if (e <= NN) g_off[e] = off[e];
    } else {
        const int m = blockIdx.x - 1;    // 0..5
        const float* src = (m == 0) ? Wl : (m == 1) ? Wr : (m == 2) ? Wl + 16384
                         : (m == 3) ? Wr + 16384 : (m == 4) ? W1 : W1 + 16384;
        for (int s = threadIdx.x; s < 4096; s += blockDim.x) {
            const int lane = s & 31, ct = (s >> 5) & 15, ks = s >> 9;
            const int n  = ct * 8 + (lane >> 2);
            const int k0 = ks * 16 + (lane & 3) * 2;
            float v[4];
            v[0] = src[(k0)     * DD + n];
            v[1] = src[(k0 + 1) * DD + n];
            v[2] = src[(k0 + 8) * DD + n];
            v[3] = src[(k0 + 9) * DD + n];
            __half h[4], l[4];
#pragma unroll
            for (int i = 0; i < 4; ++i) {
                h[i] = __float2half_rn(v[i]);
                l[i] = __float2half_rn(v[i] - __half2float(h[i]));
            }
            unsigned* o = g_Bpack + m * 16384 + s * 4;
            o[0] = packh2(h[0], h[1]);
            o[1] = packh2(h[2], h[3]);
            o[2] = packh2(l[0], l[1]);
            o[3] = packh2(l[2], l[3]);
        }
    }
}

__device__ __forceinline__ void mma_f16(float c[4], const unsigned a[4],
                                        unsigned b0, unsigned b1) {
    asm("mma.sync.aligned.m16n8k16.row.col.f32.f16.f16.f32 "
        "{%0,%1,%2,%3},{%4,%5,%6,%7},{%8,%9},{%0,%1,%2,%3};"
        : "+f"(c[0]), "+f"(c[1]), "+f"(c[2]), "+f"(c[3])
        : "r"(a[0]), "r"(a[1]), "r"(a[2]), "r"(a[3]), "r"(b0), "r"(b1));
}

// Convert fp32 A (64x128 row-major, smem) into fragment-ordered fp16 hi/lo.
__device__ __forceinline__ void convert_A(const float* __restrict__ A,
                                          unsigned* __restrict__ dst, int tid) {
    for (int s = tid; s < 4096; s += NT) {
        const int j = s & 3, lane = (s >> 2) & 31, ks = (s >> 7) & 7, rt = s >> 10;
        const int row = rt * 16 + (lane >> 2) + ((j & 1) << 3);
        const int col = ks * 16 + (lane & 3) * 2 + ((j & 2) << 2);
        const float2 vv = *(const float2*)(A + row * DD + col);
        const __half h0 = __float2half_rn(vv.x), h1 = __float2half_rn(vv.y);
        const __half l0 = __float2half_rn(vv.x - __half2float(h0));
        const __half l1 = __float2half_rn(vv.y - __half2float(h1));
        dst[s]        = packh2(h0, h1);
        dst[4096 + s] = packh2(l0, l1);
    }
}

__device__ __forceinline__ void convert_T0(const int* __restrict__ x,
                                           const float* __restrict__ attr_emb,
                                           const float* __restrict__ opt_emb,
                                           const float* __restrict__ prior,
                                           int b, unsigned* __restrict__ dst, int tid) {
    for (int s = tid; s < 4096; s += NT) {
        const int j = s & 3, lane = (s >> 2) & 31, ks = (s >> 7) & 7, rt = s >> 10;
        const int row = rt * 16 + (lane >> 2) + ((j & 1) << 3);
        const int col = ks * 16 + (lane & 3) * 2 + ((j & 2) << 2);
        const int xv = x[b * NN + row];
        const float pr = prior[row];
        const float2 a2 = *(const float2*)(attr_emb + row * DD + col);
        const float2 o2 = *(const float2*)(opt_emb + (row * KK + xv) * DD + col);
        const float v0 = (a2.x + o2.x) * pr;
        const float v1 = (a2.y + o2.y) * pr;
        const __half h0 = __float2half_rn(v0), h1 = __float2half_rn(v1);
        const __half l0 = __float2half_rn(v0 - __half2float(h0));
        const __half l1 = __float2half_rn(v1 - __half2float(h1));
        dst[s]        = packh2(h0, h1);
        dst[4096 + s] = packh2(l0, l1);
    }
}

// 64x128 @ 128x128 accumulate, B read DIRECTLY from global (L1-cached).
// Warp (rt, cg): rows rt*16..+16, coltiles ct = cg*4 + j, j<4.
__device__ __forceinline__ void gemm_ld(float c[4][4], const unsigned* __restrict__ Af,
                                        const unsigned* __restrict__ Bp,
                                        int lane, int rt, int cg) {
#pragma unroll 2
    for (int ks = 0; ks < 8; ++ks) {
        unsigned ah[4], al[4];
        *(uint4*)ah = *(const uint4*)&Af[((rt * 8 + ks) * 32 + lane) * 4];
        *(uint4*)al = *(const uint4*)&Af[4096 + ((rt * 8 + ks) * 32 + lane) * 4];
        uint4 B[4];
#pragma unroll
        for (int j = 0; j < 4; ++j)
            B[j] = *(const uint4*)&Bp[((ks * 16 + cg * 4 + j) * 32 + lane) * 4];
#pragma unroll
        for (int j = 0; j < 4; ++j) mma_f16(c[j], ah, B[j].x, B[j].y);
#pragma unroll
        for (int j = 0; j < 4; ++j) mma_f16(c[j], ah, B[j].z, B[j].w);
#pragma unroll
        for (int j = 0; j < 4; ++j) mma_f16(c[j], al, B[j].x, B[j].y);
    }
}

__device__ __forceinline__ void cinit(float c[4][4], const float* __restrict__ bias,
                                      int cg, int lane) {
#pragma unroll
    for (int j = 0; j < 4; ++j) {
        const int col = (cg * 4 + j) * 8 + (lane & 3) * 2;
        c[j][0] = bias[col];
        c[j][1] = bias[col + 1];
        c[j][2] = c[j][0];
        c[j][3] = c[j][1];
    }
}

__device__ __forceinline__ void cstore(const float c[4][4], float* __restrict__ dst,
                                       int rt, int cg, int lane) {
    const int row = rt * 16 + (lane >> 2);
#pragma unroll
    for (int j = 0; j < 4; ++j) {
        const int col = (cg * 4 + j) * 8 + (lane & 3) * 2;
        *(float2*)(dst + row * DD + col)       = make_float2(c[j][0], c[j][1]);
        *(float2*)(dst + (row + 8) * DD + col) = make_float2(c[j][2], c[j][3]);
    }
}

__device__ __forceinline__ void cstore_relu(const float c[4][4], float* __restrict__ dst,
                                            int rt, int cg, int lane) {
    const int row = rt * 16 + (lane >> 2);
#pragma unroll
    for (int j = 0; j < 4; ++j) {
        const int col = (cg * 4 + j) * 8 + (lane & 3) * 2;
        *(float2*)(dst + row * DD + col) =
            make_float2(fmaxf(c[j][0], 0.f), fmaxf(c[j][1], 0.f));
        *(float2*)(dst + (row + 8) * DD + col) =
            make_float2(fmaxf(c[j][2], 0.f), fmaxf(c[j][3], 0.f));
    }
}

__global__ __launch_bounds__(NT, 2) void gat_kernel(
    const int* __restrict__ x,
    const float* __restrict__ attr_emb, const float* __restrict__ opt_emb,
    const float* __restrict__ prior,
    const float* __restrict__ bl, const float* __restrict__ br,
    const float* __restrict__ We, const float* __restrict__ att,
    const float* __restrict__ conv_bias, const float* __restrict__ ln_g,
    const float* __restrict__ ln_b,
    const float* __restrict__ b1,
    const float* __restrict__ W2, const float* __restrict__ b2,
    float* __restrict__ out) {
    extern __shared__ float sm[];
    float* h_s   = sm;                     // 8192 floats (h; starts as T0)
    float* xl_s  = h_s + NN * DD;          // 8192
    float* xr_s  = xl_s + NN * DD;         // 8192 (A-fp16 frags / xr)
    float* ep_s  = xr_s + NN * DD;         // 768: rel[0..64] + partials [128..640)
    unsigned char* esrc_s = (unsigned char*)(ep_s + 768);  // 1024 B

    const int b = blockIdx.x;
    const int tid = threadIdx.x;
    const int lane = tid & 31;
    const int w = tid >> 5;                // 0..15
    const int g_rt = w & 3;                // GEMM rowtile
    const int g_cg = w >> 2;               // GEMM col group (0..3)

    unsigned* af_s = (unsigned*)xr_s;      // A-fragment buffer (hi 16KB + lo 16KB)

    // ---- load packed src indices ----
    for (int e = tid; e < EE; e += NT) esrc_s[e] = (unsigned char)g_srcp[e];

    // ---- h = T0 = (attr_emb + opt_emb[n, x]) * prior  (float4) ----
    for (int idx = tid; idx < NN * DD / 4; idx += NT) {
        const int n = idx >> 5, d4 = (idx & 31) * 4;
        const int xv = x[b * NN + n];
        const float pr = prior[n];
        const float4 a4 = *(const float4*)(attr_emb + n * DD + d4);
        const float4 o4 = *(const float4*)(opt_emb + (n * KK + xv) * DD + d4);
        float4 h4;
        h4.x = (a4.x + o4.x) * pr;
        h4.y = (a4.y + o4.y) * pr;
        h4.z = (a4.z + o4.z) * pr;
        h4.w = (a4.w + o4.w) * pr;
        *(float4*)(h_s + n * DD + d4) = h4;
    }
    __syncthreads();

    for (int l = 0; l < LL; ++l) {
        // ---- convert h to fp16 hi/lo fragments (into xr_s) ----
        convert_A(h_s, af_s, tid);
        __syncthreads();

        // ---- xl = h@Wl + bl ; xr = h@Wr + br  (direct-LDG B) ----
        {
            float c[4][4];
            cinit(c, bl + l * DD, g_cg, lane);
            gemm_ld(c, af_s, g_Bpack + (2 * l) * 16384, lane, g_rt, g_cg);
            cstore(c, xl_s, g_rt, g_cg, lane);

            cinit(c, br + l * DD, g_cg, lane);
            gemm_ld(c, af_s, g_Bpack + (2 * l + 1) * 16384, lane, g_rt, g_cg);
            __syncthreads();                     // all warps done reading A-frags
            cstore(c, xr_s, g_rt, g_cg, lane);   // overwrites af region
        }
        __syncthreads();                         // publish xl, xr

        // ==== fused edge phase: alpha + ONLINE softmax (base-2, 2-edge) + LN ====
        // warp w owns nodes {w, w+16, ...}; single pass over incoming edges.
        {
            const float LOG2E = 1.44269504f;
            const float4 We4  = *(const float4*)(We  + l * DD + lane * 4);
            float4 att4 = *(const float4*)(att + l * DD + lane * 4);
            att4.x *= LOG2E; att4.y *= LOG2E; att4.z *= LOG2E; att4.w *= LOG2E;
            const float4 cb4  = *(const float4*)(conv_bias + l * DD + lane * 4);
            const float4 lg4  = *(const float4*)(ln_g + l * DD + lane * 4);
            const float4 lb4  = *(const float4*)(ln_b + l * DD + lane * 4);
            for (int n = w; n < NN; n += NW) {
                const float4 xr4 = *(const float4*)(xr_s + n * DD + lane * 4);
                const int e0 = g_off[n], e1 = g_off[n + 1];
                float m = -INFINITY, s = 0.f;
                float v0 = 0.f, v1 = 0.f, v2 = 0.f, v3 = 0.f;
                int i = e0;
                for (; i + 1 < e1; i += 2) {
                    // edge i
                    const float4 xa = *(const float4*)(xl_s + (int)esrc_s[i] * DD + lane * 4);
                    const float ea0 = g_eap[i];
                    float za0 = xa.x + xr4.x + ea0 * We4.x;
                    float za1 = xa.y + xr4.y + ea0 * We4.y;
                    float za2 = xa.z + xr4.z + ea0 * We4.z;
                    float za3 = xa.w + xr4.w + ea0 * We4.w;
                    za0 = za0 > 0.f ? za0 : 0.2f * za0;
                    za1 = za1 > 0.f ? za1 : 0.2f * za1;
                    za2 = za2 > 0.f ? za2 : 0.2f * za2;
                    za3 = za3 > 0.f ? za3 : 0.2f * za3;
                    float pa = za0 * att4.x + za1 * att4.y + za2 * att4.z + za3 * att4.w;
                    // edge i+1
                    const float4 xb = *(const float4*)(xl_s + (int)esrc_s[i + 1] * DD + lane * 4);
                    const float ea1 = g_eap[i + 1];
                    float zb0 = xb.x + xr4.x + ea1 * We4.x;
                    float zb1 = xb.y + xr4.y + ea1 * We4.y;
                    float zb2 = xb.z + xr4.z + ea1 * We4.z;
                    float zb3 = xb.w + xr4.w + ea1 * We4.w;
                    zb0 = zb0 > 0.f ? zb0 : 0.2f * zb0;
                    zb1 = zb1 > 0.f ? zb1 : 0.2f * zb1;
                    zb2 = zb2 > 0.f ? zb2 : 0.2f * zb2;
                    zb3 = zb3 > 0.f ? zb3 : 0.2f * zb3;
                    float pb = zb0 * att4.x + zb1 * att4.y + zb2 * att4.z + zb3 * att4.w;
                    // two independent reduction chains
                    pa += __shfl_xor_sync(0xffffffffu, pa, 1);
                    pb += __shfl_xor_sync(0xffffffffu, pb, 1);
                    pa += __shfl_xor_sync(0xffffffffu, pa, 2);
                    pb += __shfl_xor_sync(0xffffffffu, pb, 2);
                    pa += __shfl_xor_sync(0xffffffffu, pa, 4);
                    pb += __shfl_xor_sync(0xffffffffu, pb, 4);
                    // combined online update (base-2)
                    const float mn = fmaxf(m, fmaxf(pa, pb));
                    const float cm = exp2f(m - mn);
                    const float ca = exp2f(pa - mn);
                    const float cb = exp2f(pb - mn);
                    s  = s * cm + ca + cb;
                    v0 = v0 * cm + ca * xa.x + cb * xb.x;
                    v1 = v1 * cm + ca * xa.y + cb * xb.y;
                    v2 = v2 * cm + ca * xa.z + cb * xb.z;
                    v3 = v3 * cm + ca * xa.w + cb * xb.w;
                    m = mn;
                }
                if (i < e1) {                      // odd tail edge
                    const float4 xa = *(const float4*)(xl_s + (int)esrc_s[i] * DD + lane * 4);
                    const float ea0 = g_eap[i];
                    float za0 = xa.x + xr4.x + ea0 * We4.x;
                    float za1 = xa.y + xr4.y + ea0 * We4.y;
                    float za2 = xa.z + xr4.z + ea0 * We4.z;
                    float za3 = xa.w + xr4.w + ea0 * We4.w;
                    za0 = za0 > 0.f ? za0 : 0.2f * za0;
                    za1 = za1 > 0.f ? za1 : 0.2f * za1;
                    za2 = za2 > 0.f ? za2 : 0.2f * za2;
                    za3 = za3 > 0.f ? za3 : 0.2f * za3;
                    float pa = za0 * att4.x + za1 * att4.y + za2 * att4.z + za3 * att4.w;
                    pa += __shfl_xor_sync(0xffffffffu, pa, 1);
                    pa += __shfl_xor_sync(0xffffffffu, pa, 2);
                    pa += __shfl_xor_sync(0xffffffffu, pa, 4);
                    const float mn = fmaxf(m, pa);
                    const float cm = exp2f(m - mn);
                    const float ca = exp2f(pa - mn);
                    s  = s * cm + ca;
                    v0 = v0 * cm + ca * xa.x;
                    v1 = v1 * cm + ca * xa.y;
                    v2 = v2 * cm + ca * xa.z;
                    v3 = v3 * cm + ca * xa.w;
                }
                if (e1 > e0) {
                    const float inv = 1.f / s;
                    v0 *= inv; v1 *= inv; v2 *= inv; v3 *= inv;
                }
                v0 += cb4.x; v1 += cb4.y; v2 += cb4.z; v3 += cb4.w;
                float sum = v0 + v1 + v2 + v3;
                float sq  = v0*v0 + v1*v1 + v2*v2 + v3*v3;
#pragma unroll
                for (int o = 16; o; o >>= 1) {
                    sum += __shfl_xor_sync(0xffffffffu, sum, o);
                    sq  += __shfl_xor_sync(0xffffffffu, sq, o);
                }
                const float mu = sum * (1.f / DD);
                const float var = sq * (1.f / DD) - mu * mu;
                const float rstd = rsqrtf(var + 1e-5f);
                float t0v = (v0 - mu) * rstd * lg4.x + lb4.x;
                float t1v = (v1 - mu) * rstd * lg4.y + lb4.y;
                float t2v = (v2 - mu) * rstd * lg4.z + lb4.z;
                float t3v = (v3 - mu) * rstd * lg4.w + lb4.w;
                t0v = t0v > 0.f ? t0v : expm1f(t0v);
                t1v = t1v > 0.f ? t1v : expm1f(t1v);
                t2v = t2v > 0.f ? t2v : expm1f(t2v);
                t3v = t3v > 0.f ? t3v : expm1f(t3v);
                float4 hv = *(const float4*)(h_s + n * DD + lane * 4);
                hv.x += t0v; hv.y += t1v; hv.z += t2v; hv.w += t3v;
                *(float4*)(h_s + n * DD + lane * 4) = hv;
            }
        }
        __syncthreads();                   // publish h before next convert
    }

    // ---- MLP: q = relu([T0, h] @ W1 + b1) -> xl_s  (two K=128 passes) ----
    {
        float c[4][4];
        cinit(c, b1, g_cg, lane);
        convert_T0(x, attr_emb, opt_emb, prior, b, af_s, tid);
        __syncthreads();
        gemm_ld(c, af_s, g_Bpack + 4 * 16384, lane, g_rt, g_cg);
        __syncthreads();                   // all warps done with T0 frags
        convert_A(h_s, af_s, tid);
        __syncthreads();
        gemm_ld(c, af_s, g_Bpack + 5 * 16384, lane, g_rt, g_cg);
        cstore_relu(c, xl_s, g_rt, g_cg, lane);
    }
    __syncthreads();

    float* rel_s = ep_s;          // [0..63], relsum at [64], partials at [128..640)

    // ---- rel[n] = sigmoid(q[n].W2 + b2)   (warp per node) ----
    {
        const long long OR = (long long)NB * DD;
        const float4 w24 = *(const float4*)(W2 + lane * 4);
        for (int n = w; n < NN; n += NW) {
            const float4 qv = *(const float4*)(xl_s + n * DD + lane * 4);
            float p = qv.x * w24.x + qv.y * w24.y + qv.z * w24.z + qv.w * w24.w;
#pragma unroll
            for (int o = 16; o; o >>= 1) p += __shfl_xor_sync(0xffffffffu, p, o);
            if (lane == 0) {
                const float r = 1.f / (1.f + expf(-(p + b2[0])));
                rel_s[n] = r;
                out[OR + (long long)b * NN + n] = r;
            }
        }
    }
    __syncthreads();

    // ---- rel sum (warp 0) ----
    if (w == 0) {
        float v = rel_s[lane] + rel_s[lane + 32];
#pragma unroll
        for (int o = 16; o; o >>= 1) v += __shfl_xor_sync(0xffffffffu, v, o);
        if (lane == 0) rel_s[64] = v;
    }

    // ---- f_scale partials (4-way) ----
    {
        const int d = tid & 127;
        const int q = tid >> 7;            // 0..3
        float acc = 0.f;
        for (int n = q; n < NN; n += 4)
            acc = fmaf(h_s[n * DD + d], rel_s[n], acc);
        ep_s[128 + q * DD + d] = acc;
    }

    // ---- hat_T output: [T0 (recomputed), h]  (float4) ----
    {
        const long long OH = (long long)NB * DD + (long long)NB * NN;
        for (int idx = tid; idx < NN * DD / 4; idx += NT) {
            const int n = idx >> 5, d4 = (idx & 31) * 4;
            const int xv = x[b * NN + n];
            const float pr = prior[n];
            const float4 a4 = *(const float4*)(attr_emb + n * DD + d4);
            const float4 o4 = *(const float4*)(opt_emb + (n * KK + xv) * DD + d4);
            float4 t4;
            t4.x = (a4.x + o4.x) * pr;
            t4.y = (a4.y + o4.y) * pr;
            t4.z = (a4.z + o4.z) * pr;
            t4.w = (a4.w + o4.w) * pr;
            const long long base = OH + ((long long)b * NN + n) * (2 * DD);
            *(float4*)(out + base + d4) = t4;
            *(float4*)(out + base + DD + d4) = *(const float4*)(h_s + n * DD + d4);
        }
    }
    __syncthreads();

    if (tid < DD) {
        const float num = ep_s[128 + tid] + ep_s[256 + tid] +
                          ep_s[384 + tid] + ep_s[512 + tid];
        out[(long long)b * DD + tid] = num / (rel_s[64] + 1e-8f);
    }
}

extern "C" void kernel_launch(void* const* d_in, const int* in_sizes, int n_in,
                              void* d_out, int out_size) {
    const int*   x         = (const int*)d_in[0];
    const int*   ei        = (const int*)d_in[1];
    const float* ea        = (const float*)d_in[2];
    const float* attr_emb  = (const float*)d_in[3];
    const float* opt_emb   = (const float*)d_in[4];
    const float* prior     = (const float*)d_in[5];
    const float* Wl        = (const float*)d_in[6];
    const float* bl        = (const float*)d_in[7];
    const float* Wr        = (const float*)d_in[8];
    const float* br        = (const float*)d_in[9];
    const float* We        = (const float*)d_in[10];
    const float* att       = (const float*)d_in[11];
    const float* conv_bias = (const float*)d_in[12];
    const float* ln_g      = (const float*)d_in[13];
    const float* ln_b      = (const float*)d_in[14];
    const float* W1        = (const float*)d_in[15];
    const float* b1        = (const float*)d_in[16];
    const float* W2        = (const float*)d_in[17];
    const float* b2        = (const float*)d_in[18];
    float* out = (float*)d_out;

    const size_t smem = (3 * NN * DD + 768) * sizeof(float) + EE;
    cudaFuncSetAttribute(gat_kernel, cudaFuncAttributeMaxDynamicSharedMemorySize, (int)smem);

    setup_kernel<<<7, EE>>>(ei, ea, Wl, Wr, W1);
    gat_kernel<<<NB, NT, smem>>>(x, attr_emb, opt_emb, prior,
                                 bl, br, We, att, conv_bias,
                                 ln_g, ln_b, b1, W2, b2, out);
}

// round 17
// speedup vs baseline: 1.4966x; 1.4966x over previous
#include <cuda_runtime.h>
#include <cuda_bf16.h>
#include <cuda_fp16.h>
#include <math.h>

#define NB 1024   // batches
#define NN 64     // nodes
#define DD 128    // feature dim
#define EE 1024   // edges
#define HH 4      // heads
#define KK 5
#define LL 2
#define NT 512    // threads per CTA
#define NW 16     // warps per CTA

// Edge data sorted by dst (CSR order), built once per launch
__device__ int   g_off[NN + 1];
__device__ int   g_srcp[EE];
__device__ float g_eap[EE];

// W matrices as fp16 hi/lo packed in m16n8k16 B-fragment order:
// mat m: slot s = (ks*16 + ct)*32 + lane; u32[4] = {bhi0, bhi1, blo0, blo1}
// mats: 0=Wl0 1=Wr0 2=Wl1 3=Wr1 4=W1[0:128] 5=W1[128:256]
__device__ unsigned g_Bpack[6 * 16384];

__device__ __forceinline__ unsigned packh2(__half a, __half b) {
    __half2 h; h.x = a; h.y = b;
    return *(const unsigned*)&h;
}

// Merged setup: block 0 = parallel stable CSR build, blocks 1..6 = W packing.
__global__ __launch_bounds__(EE) void setup_kernel(const int* __restrict__ ei,
                                                   const float* __restrict__ ea,
                                                   const float* __restrict__ Wl,
                                                   const float* __restrict__ Wr,
                                                   const float* __restrict__ W1) {
    if (blockIdx.x == 0) {
        // Stable bucket sort by dst, O(1)-depth per edge:
        // rank = chunk-prefix(dst) + rank-within-32-edge-chunk (via match_any).
        __shared__ int cnt[32][NN];    // per-chunk per-dst counts -> exclusive prefix
        __shared__ int deg[NN];
        __shared__ int off[NN + 1];
        const int e = threadIdx.x;     // 0..1023
        const int chunk = e >> 5;
        const int lane = e & 31;
        for (int i = e; i < 32 * NN; i += EE) (&cnt[0][0])[i] = 0;
        __syncthreads();
        const int d = ei[EE + e];
        const unsigned mm = __match_any_sync(0xffffffffu, d);
        const int rank_in_chunk = __popc(mm & ((1u << lane) - 1u));
        if ((int)(__ffs(mm) - 1) == lane) cnt[chunk][d] = __popc(mm);
        __syncthreads();
        if (e < NN) {
            int run = 0;
#pragma unroll 4
            for (int c = 0; c < 32; ++c) {
                const int t = cnt[c][e];
                cnt[c][e] = run;
                run += t;
            }
            deg[e] = run;
        }
        __syncthreads();
        if (e == 0) {
            int s = 0;
            for (int i = 0; i < NN; ++i) { off[i] = s; s += deg[i]; }
            off[NN] = s;
        }
        __syncthreads();
        const int p = off[d] + cnt[chunk][d] + rank_in_chunk;
        g_srcp[p] = ei[e];
        g_eap[p]  = ea[e];
        if (e <= NN) g_off[e] = off[e];
    } else {
        const int m = blockIdx.x - 1;    // 0..5
        const float* src = (m == 0) ? Wl : (m == 1) ? Wr : (m == 2) ? Wl + 16384
                         : (m == 3) ? Wr + 16384 : (m == 4) ? W1 : W1 + 16384;
        for (int s = threadIdx.x; s < 4096; s += blockDim.x) {
            const int lane = s & 31, ct = (s >> 5) & 15, ks = s >> 9;
            const int n  = ct * 8 + (lane >> 2);
            const int k0 = ks * 16 + (lane & 3) * 2;
            float v[4];
            v[0] = src[(k0)     * DD + n];
            v[1] = src[(k0 + 1) * DD + n];
            v[2] = src[(k0 + 8) * DD + n];
            v[3] = src[(k0 + 9) * DD + n];
            __half h[4], l[4];
#pragma unroll
            for (int i = 0; i < 4; ++i) {
                h[i] = __float2half_rn(v[i]);
                l[i] = __float2half_rn(v[i] - __half2float(h[i]));
            }
            unsigned* o = g_Bpack + m * 16384 + s * 4;
            o[0] = packh2(h[0], h[1]);
            o[1] = packh2(h[2], h[3]);
            o[2] = packh2(l[0], l[1]);
            o[3] = packh2(l[2], l[3]);
        }
    }
}

__device__ __forceinline__ void mma_f16(float c[4], const unsigned a[4],
                                        unsigned b0, unsigned b1) {
    asm("mma.sync.aligned.m16n8k16.row.col.f32.f16.f16.f32 "
        "{%0,%1,%2,%3},{%4,%5,%6,%7},{%8,%9},{%0,%1,%2,%3};"
        : "+f"(c[0]), "+f"(c[1]), "+f"(c[2]), "+f"(c[3])
        : "r"(a[0]), "r"(a[1]), "r"(a[2]), "r"(a[3]), "r"(b0), "r"(b1));
}

// Convert fp32 A (64x128 row-major, smem) into fragment-ordered fp16 hi/lo.
__device__ __forceinline__ void convert_A(const float* __restrict__ A,
                                          unsigned* __restrict__ dst, int tid) {
    for (int s = tid; s < 4096; s += NT) {
        const int j = s & 3, lane = (s >> 2) & 31, ks = (s >> 7) & 7, rt = s >> 10;
        const int row = rt * 16 + (lane >> 2) + ((j & 1) << 3);
        const int col = ks * 16 + (lane & 3) * 2 + ((j & 2) << 2);
        const float2 vv = *(const float2*)(A + row * DD + col);
        const __half h0 = __float2half_rn(vv.x), h1 = __float2half_rn(vv.y);
        const __half l0 = __float2half_rn(vv.x - __half2float(h0));
        const __half l1 = __float2half_rn(vv.y - __half2float(h1));
        dst[s]        = packh2(h0, h1);
        dst[4096 + s] = packh2(l0, l1);
    }
}

__device__ __forceinline__ void convert_T0(const int* __restrict__ x,
                                           const float* __restrict__ attr_emb,
                                           const float* __restrict__ opt_emb,
                                           const float* __restrict__ prior,
                                           int b, unsigned* __restrict__ dst, int tid) {
    for (int s = tid; s < 4096; s += NT) {
        const int j = s & 3, lane = (s >> 2) & 31, ks = (s >> 7) & 7, rt = s >> 10;
        const int row = rt * 16 + (lane >> 2) + ((j & 1) << 3);
        const int col = ks * 16 + (lane & 3) * 2 + ((j & 2) << 2);
        const int xv = x[b * NN + row];
        const float pr = prior[row];
        const float2 a2 = *(const float2*)(attr_emb + row * DD + col);
        const float2 o2 = *(const float2*)(opt_emb + (row * KK + xv) * DD + col);
        const float v0 = (a2.x + o2.x) * pr;
        const float v1 = (a2.y + o2.y) * pr;
        const __half h0 = __float2half_rn(v0), h1 = __float2half_rn(v1);
        const __half l0 = __float2half_rn(v0 - __half2float(h0));
        const __half l1 = __float2half_rn(v1 - __half2float(h1));
        dst[s]        = packh2(h0, h1);
        dst[4096 + s] = packh2(l0, l1);
    }
}

// 64x128 @ 128x128 accumulate, B read DIRECTLY from global (L1-cached).
// Warp (rt, cg): rows rt*16..+16, coltiles ct = cg*4 + j, j<4.
__device__ __forceinline__ void gemm_ld(float c[4][4], const unsigned* __restrict__ Af,
                                        const unsigned* __restrict__ Bp,
                                        int lane, int rt, int cg) {
#pragma unroll 2
    for (int ks = 0; ks < 8; ++ks) {
        unsigned ah[4], al[4];
        *(uint4*)ah = *(const uint4*)&Af[((rt * 8 + ks) * 32 + lane) * 4];
        *(uint4*)al = *(const uint4*)&Af[4096 + ((rt * 8 + ks) * 32 + lane) * 4];
        uint4 B[4];
#pragma unroll
        for (int j = 0; j < 4; ++j)
            B[j] = *(const uint4*)&Bp[((ks * 16 + cg * 4 + j) * 32 + lane) * 4];
#pragma unroll
        for (int j = 0; j < 4; ++j) mma_f16(c[j], ah, B[j].x, B[j].y);
#pragma unroll
        for (int j = 0; j < 4; ++j) mma_f16(c[j], ah, B[j].z, B[j].w);
#pragma unroll
        for (int j = 0; j < 4; ++j) mma_f16(c[j], al, B[j].x, B[j].y);
    }
}

__device__ __forceinline__ void cinit(float c[4][4], const float* __restrict__ bias,
                                      int cg, int lane) {
#pragma unroll
    for (int j = 0; j < 4; ++j) {
        const int col = (cg * 4 + j) * 8 + (lane & 3) * 2;
        c[j][0] = bias[col];
        c[j][1] = bias[col + 1];
        c[j][2] = c[j][0];
        c[j][3] = c[j][1];
    }
}

__device__ __forceinline__ void cstore(const float c[4][4], float* __restrict__ dst,
                                       int rt, int cg, int lane) {
    const int row = rt * 16 + (lane >> 2);
#pragma unroll
    for (int j = 0; j < 4; ++j) {
        const int col = (cg * 4 + j) * 8 + (lane & 3) * 2;
        *(float2*)(dst + row * DD + col)       = make_float2(c[j][0], c[j][1]);
        *(float2*)(dst + (row + 8) * DD + col) = make_float2(c[j][2], c[j][3]);
    }
}

__device__ __forceinline__ void cstore_relu(const float c[4][4], float* __restrict__ dst,
                                            int rt, int cg, int lane) {
    const int row = rt * 16 + (lane >> 2);
#pragma unroll
    for (int j = 0; j < 4; ++j) {
        const int col = (cg * 4 + j) * 8 + (lane & 3) * 2;
        *(float2*)(dst + row * DD + col) =
            make_float2(fmaxf(c[j][0], 0.f), fmaxf(c[j][1], 0.f));
        *(float2*)(dst + (row + 8) * DD + col) =
            make_float2(fmaxf(c[j][2], 0.f), fmaxf(c[j][3], 0.f));
    }
}

__global__ __launch_bounds__(NT, 2) void gat_kernel(
    const int* __restrict__ x,
    const float* __restrict__ attr_emb, const float* __restrict__ opt_emb,
    const float* __restrict__ prior,
    const float* __restrict__ bl, const float* __restrict__ br,
    const float* __restrict__ We, const float* __restrict__ att,
    const float* __restrict__ conv_bias, const float* __restrict__ ln_g,
    const float* __restrict__ ln_b,
    const float* __restrict__ b1,
    const float* __restrict__ W2, const float* __restrict__ b2,
    float* __restrict__ out) {
    extern __shared__ float sm[];
    float* h_s   = sm;                     // 8192 floats (h; starts as T0)
    float* xl_s  = h_s + NN * DD;          // 8192
    float* xr_s  = xl_s + NN * DD;         // 8192 (A-fp16 frags / xr)
    float* ep_s  = xr_s + NN * DD;         // 768: rel[0..64] + partials [128..640)
    unsigned char* esrc_s = (unsigned char*)(ep_s + 768);  // 1024 B

    const int b = blockIdx.x;
    const int tid = threadIdx.x;
    const int lane = tid & 31;
    const int w = tid >> 5;                // 0..15
    const int g_rt = w & 3;                // GEMM rowtile
    const int g_cg = w >> 2;               // GEMM col group (0..3)

    unsigned* af_s = (unsigned*)xr_s;      // A-fragment buffer (hi 16KB + lo 16KB)

    // ---- load packed src indices ----
    for (int e = tid; e < EE; e += NT) esrc_s[e] = (unsigned char)g_srcp[e];

    // ---- h = T0 = (attr_emb + opt_emb[n, x]) * prior  (float4) ----
    for (int idx = tid; idx < NN * DD / 4; idx += NT) {
        const int n = idx >> 5, d4 = (idx & 31) * 4;
        const int xv = x[b * NN + n];
        const float pr = prior[n];
        const float4 a4 = *(const float4*)(attr_emb + n * DD + d4);
        const float4 o4 = *(const float4*)(opt_emb + (n * KK + xv) * DD + d4);
        float4 h4;
        h4.x = (a4.x + o4.x) * pr;
        h4.y = (a4.y + o4.y) * pr;
        h4.z = (a4.z + o4.z) * pr;
        h4.w = (a4.w + o4.w) * pr;
        *(float4*)(h_s + n * DD + d4) = h4;
    }
    __syncthreads();

    for (int l = 0; l < LL; ++l) {
        // ---- convert h to fp16 hi/lo fragments (into xr_s) ----
        convert_A(h_s, af_s, tid);
        __syncthreads();

        // ---- xl = h@Wl + bl ; xr = h@Wr + br  (direct-LDG B) ----
        {
            float c[4][4];
            cinit(c, bl + l * DD, g_cg, lane);
            gemm_ld(c, af_s, g_Bpack + (2 * l) * 16384, lane, g_rt, g_cg);
            cstore(c, xl_s, g_rt, g_cg, lane);

            cinit(c, br + l * DD, g_cg, lane);
            gemm_ld(c, af_s, g_Bpack + (2 * l + 1) * 16384, lane, g_rt, g_cg);
            __syncthreads();                     // all warps done reading A-frags
            cstore(c, xr_s, g_rt, g_cg, lane);   // overwrites af region
        }
        __syncthreads();                         // publish xl, xr

        // ==== fused edge phase: alpha + ONLINE softmax + aggregate + LN ====
        // warp w owns nodes {w, w+16, ...}; single pass over incoming edges.
        {
            const float4 We4  = *(const float4*)(We  + l * DD + lane * 4);
            const float4 att4 = *(const float4*)(att + l * DD + lane * 4);
            const float4 cb4  = *(const float4*)(conv_bias + l * DD + lane * 4);
            const float4 lg4  = *(const float4*)(ln_g + l * DD + lane * 4);
            const float4 lb4  = *(const float4*)(ln_b + l * DD + lane * 4);
            for (int n = w; n < NN; n += NW) {
                const float4 xr4 = *(const float4*)(xr_s + n * DD + lane * 4);
                const int e0 = g_off[n], e1 = g_off[n + 1];
                float m = -INFINITY, s = 0.f;
                float v0 = 0.f, v1 = 0.f, v2 = 0.f, v3 = 0.f;
#pragma unroll 2
                for (int i = e0; i < e1; ++i) {
                    const int sidx = esrc_s[i];
                    const float eav = g_eap[i];
                    const float4 xl4 = *(const float4*)(xl_s + sidx * DD + lane * 4);
                    float z0 = xl4.x + xr4.x + eav * We4.x;
                    float z1 = xl4.y + xr4.y + eav * We4.y;
                    float z2 = xl4.z + xr4.z + eav * We4.z;
                    float z3 = xl4.w + xr4.w + eav * We4.w;
                    z0 = z0 > 0.f ? z0 : 0.2f * z0;
                    z1 = z1 > 0.f ? z1 : 0.2f * z1;
                    z2 = z2 > 0.f ? z2 : 0.2f * z2;
                    z3 = z3 > 0.f ? z3 : 0.2f * z3;
                    float p = z0 * att4.x + z1 * att4.y + z2 * att4.z + z3 * att4.w;
                    p += __shfl_xor_sync(0xffffffffu, p, 1);
                    p += __shfl_xor_sync(0xffffffffu, p, 2);
                    p += __shfl_xor_sync(0xffffffffu, p, 4);
                    // p = alpha[e, head] in all 8 lanes of the head group
                    const float mn = fmaxf(m, p);
                    const float cm = __expf(m - mn);   // first iter: exp(-inf)=0
                    const float cp = __expf(p - mn);
                    s  = s * cm + cp;
                    v0 = v0 * cm + cp * xl4.x;
                    v1 = v1 * cm + cp * xl4.y;
                    v2 = v2 * cm + cp * xl4.z;
                    v3 = v3 * cm + cp * xl4.w;
                    m = mn;
                }
                if (e1 > e0) {
                    const float inv = 1.f / s;
                    v0 *= inv; v1 *= inv; v2 *= inv; v3 *= inv;
                }
                v0 += cb4.x; v1 += cb4.y; v2 += cb4.z; v3 += cb4.w;
                float sum = v0 + v1 + v2 + v3;
                float sq  = v0*v0 + v1*v1 + v2*v2 + v3*v3;
#pragma unroll
                for (int o = 16; o; o >>= 1) {
                    sum += __shfl_xor_sync(0xffffffffu, sum, o);
                    sq  += __shfl_xor_sync(0xffffffffu, sq, o);
                }
                const float mu = sum * (1.f / DD);
                const float var = sq * (1.f / DD) - mu * mu;
                const float rstd = rsqrtf(var + 1e-5f);
                float t0v = (v0 - mu) * rstd * lg4.x + lb4.x;
                float t1v = (v1 - mu) * rstd * lg4.y + lb4.y;
                float t2v = (v2 - mu) * rstd * lg4.z + lb4.z;
                float t3v = (v3 - mu) * rstd * lg4.w + lb4.w;
                t0v = t0v > 0.f ? t0v : expm1f(t0v);
                t1v = t1v > 0.f ? t1v : expm1f(t1v);
                t2v = t2v > 0.f ? t2v : expm1f(t2v);
                t3v = t3v > 0.f ? t3v : expm1f(t3v);
                float4 hv = *(const float4*)(h_s + n * DD + lane * 4);
                hv.x += t0v; hv.y += t1v; hv.z += t2v; hv.w += t3v;
                *(float4*)(h_s + n * DD + lane * 4) = hv;
            }
        }
        __syncthreads();                   // publish h before next convert
    }

    // ---- MLP: q = relu([T0, h] @ W1 + b1) -> xl_s  (two K=128 passes) ----
    {
        float c[4][4];
        cinit(c, b1, g_cg, lane);
        convert_T0(x, attr_emb, opt_emb, prior, b, af_s, tid);
        __syncthreads();
        gemm_ld(c, af_s, g_Bpack + 4 * 16384, lane, g_rt, g_cg);
        __syncthreads();                   // all warps done with T0 frags
        convert_A(h_s, af_s, tid);
        __syncthreads();
        gemm_ld(c, af_s, g_Bpack + 5 * 16384, lane, g_rt, g_cg);
        cstore_relu(c, xl_s, g_rt, g_cg, lane);
    }
    __syncthreads();

    float* rel_s = ep_s;          // [0..63], relsum at [64], partials at [128..640)

    // ---- rel[n] = sigmoid(q[n].W2 + b2)   (warp per node) ----
    {
        const long long OR = (long long)NB * DD;
        const float4 w24 = *(const float4*)(W2 + lane * 4);
        for (int n = w; n < NN; n += NW) {
            const float4 qv = *(const float4*)(xl_s + n * DD + lane * 4);
            float p = qv.x * w24.x + qv.y * w24.y + qv.z * w24.z + qv.w * w24.w;
#pragma unroll
            for (int o = 16; o; o >>= 1) p += __shfl_xor_sync(0xffffffffu, p, o);
            if (lane == 0) {
                const float r = 1.f / (1.f + expf(-(p + b2[0])));
                rel_s[n] = r;
                out[OR + (long long)b * NN + n] = r;
            }
        }
    }
    __syncthreads();

    // ---- rel sum (warp 0) ----
    if (w == 0) {
        float v = rel_s[lane] + rel_s[lane + 32];
#pragma unroll
        for (int o = 16; o; o >>= 1) v += __shfl_xor_sync(0xffffffffu, v, o);
        if (lane == 0) rel_s[64] = v;
    }

    // ---- f_scale partials (4-way) ----
    {
        const int d = tid & 127;
        const int q = tid >> 7;            // 0..3
        float acc = 0.f;
        for (int n = q; n < NN; n += 4)
            acc = fmaf(h_s[n * DD + d], rel_s[n], acc);
        ep_s[128 + q * DD + d] = acc;
    }

    // ---- hat_T output: [T0 (recomputed), h]  (float4) ----
    {
        const long long OH = (long long)NB * DD + (long long)NB * NN;
        for (int idx = tid; idx < NN * DD / 4; idx += NT) {
            const int n = idx >> 5, d4 = (idx & 31) * 4;
            const int xv = x[b * NN + n];
            const float pr = prior[n];
            const float4 a4 = *(const float4*)(attr_emb + n * DD + d4);
            const float4 o4 = *(const float4*)(opt_emb + (n * KK + xv) * DD + d4);
            float4 t4;
            t4.x = (a4.x + o4.x) * pr;
            t4.y = (a4.y + o4.y) * pr;
            t4.z = (a4.z + o4.z) * pr;
            t4.w = (a4.w + o4.w) * pr;
            const long long base = OH + ((long long)b * NN + n) * (2 * DD);
            *(float4*)(out + base + d4) = t4;
            *(float4*)(out + base + DD + d4) = *(const float4*)(h_s + n * DD + d4);
        }
    }
    __syncthreads();

    if (tid < DD) {
        const float num = ep_s[128 + tid] + ep_s[256 + tid] +
                          ep_s[384 + tid] + ep_s[512 + tid];
        out[(long long)b * DD + tid] = num / (rel_s[64] + 1e-8f);
    }
}

extern "C" void kernel_launch(void* const* d_in, const int* in_sizes, int n_in,
                              void* d_out, int out_size) {
    const int*   x         = (const int*)d_in[0];
    const int*   ei        = (const int*)d_in[1];
    const float* ea        = (const float*)d_in[2];
    const float* attr_emb  = (const float*)d_in[3];
    const float* opt_emb   = (const float*)d_in[4];
    const float* prior     = (const float*)d_in[5];
    const float* Wl        = (const float*)d_in[6];
    const float* bl        = (const float*)d_in[7];
    const float* Wr        = (const float*)d_in[8];
    const float* br        = (const float*)d_in[9];
    const float* We        = (const float*)d_in[10];
    const float* att       = (const float*)d_in[11];
    const float* conv_bias = (const float*)d_in[12];
    const float* ln_g      = (const float*)d_in[13];
    const float* ln_b      = (const float*)d_in[14];
    const float* W1        = (const float*)d_in[15];
    const float* b1        = (const float*)d_in[16];
    const float* W2        = (const float*)d_in[17];
    const float* b2        = (const float*)d_in[18];
    float* out = (float*)d_out;

    const size_t smem = (3 * NN * DD + 768) * sizeof(float) + EE;
    cudaFuncSetAttribute(gat_kernel, cudaFuncAttributeMaxDynamicSharedMemorySize, (int)smem);

    setup_kernel<<<7, EE>>>(ei, ea, Wl, Wr, W1);
    gat_kernel<<<NB, NT, smem>>>(x, attr_emb, opt_emb, prior,
                                 bl, br, We, att, conv_bias,
                                 ln_g, ln_b, b1, W2, b2, out);
}